// round 13
// baseline (speedup 1.0000x reference)
#include <cuda_runtime.h>
#include <cuda_bf16.h>
#include <cstdint>
#include <math.h>

#define BDIM 64
#define TDIM 768
#define DDIM 128
#define EDIM 64
#define HDIM 128
#define ODIM 10
#define TC   256
#define G4   512
#define EPSP 5.0f
#define FULLM 0xffffffffu

__device__ __align__(16) float g_emb[BDIM * TC * EDIM];
__device__ __align__(16) float g_zx[(size_t)BDIM * TC * G4];   // permuted cols j' = 4h+g
__device__ __align__(16) float g_whhT[HDIM * G4];              // [hsum][j'=4h+g]
__device__ __align__(16) float g_wihT[EDIM * G4];              // [e][j] orig order (k3 only)
__device__ __align__(16) float g_convW[384 * EDIM];
__device__ __align__(16) float g_bias[G4];                     // permuted [j'=4h+g]
__device__ float g_part_s[256 * EDIM];
__device__ float g_part_ss[256 * EDIM];
__device__ float g_scale[EDIM];
__device__ float g_shift[EDIM];

__device__ __forceinline__ float sigf(float x) { return 1.0f / (1.0f + expf(-x)); }

__device__ __forceinline__ unsigned long long pk2(float lo, float hi) {
    unsigned long long d; asm("mov.b64 %0, {%1,%2};" : "=l"(d) : "f"(lo), "f"(hi)); return d;
}
__device__ __forceinline__ void upk2(unsigned long long v, float& lo, float& hi) {
    asm("mov.b64 {%0,%1}, %2;" : "=f"(lo), "=f"(hi) : "l"(v));
}
__device__ __forceinline__ unsigned long long fma2(unsigned long long a, unsigned long long b, unsigned long long c) {
    unsigned long long d; asm("fma.rn.f32x2 %0, %1, %2, %3;" : "=l"(d) : "l"(a), "l"(b), "l"(c)); return d;
}

// ---------------- K0 ----------------
__global__ __launch_bounds__(256) void k0_prep(
    const float* __restrict__ wih, const float* __restrict__ whh,
    const float* __restrict__ bih, const float* __restrict__ bhh,
    const float* __restrict__ conv_w) {
    int i = blockIdx.x * 256 + threadIdx.x;
    if (i < 65536) {                       // whhT[hsum][4h+g] = whh[g*128+h][hsum]
        int hsum = i >> 9, jp = i & 511;
        int h = jp >> 2, g = jp & 3;
        g_whhT[i] = whh[((g << 7) + h) * HDIM + hsum];
    } else if (i < 65536 + 32768) {        // wihT[e][j] orig order
        int m = i - 65536;
        int e = m >> 9, j = m & 511;
        g_wihT[m] = wih[j * EDIM + e];
    } else if (i < 65536 + 32768 + 24576) {
        int m = i - 65536 - 32768;
        int q = m >> 6, e = m & 63;
        int k = q >> 7, d = q & 127;
        g_convW[m] = conv_w[e * 384 + d * 3 + k];
    } else if (i < 65536 + 32768 + 24576 + 512) {
        int jp = i - 65536 - 32768 - 24576;
        int h = jp >> 2, g = jp & 3;
        int r = (g << 7) + h;
        g_bias[jp] = bih[r] + bhh[r];
    }
}

// ---------------- K1 ----------------
__global__ __launch_bounds__(256) void k1_conv(
    const float* __restrict__ in, const float* __restrict__ conv_b) {
    __shared__ float xn[48 * 128];
    __shared__ float invn[48];
    int tid = threadIdx.x;
    int b = blockIdx.x >> 4, seg = blockIdx.x & 15;

    const float4* src = (const float4*)(in + ((size_t)b * TDIM + seg * 48) * DDIM);
    float4* d4 = (float4*)xn;
    for (int i = tid; i < 1536; i += 256) d4[i] = src[i];
    __syncthreads();

    int warp = tid >> 5, lane = tid & 31;
    for (int r = warp; r < 48; r += 8) {
        float v = 0.f;
        #pragma unroll
        for (int q = 0; q < 4; q++) { float x = xn[r * 128 + lane + q * 32]; v += x * x; }
        #pragma unroll
        for (int off = 16; off; off >>= 1) v += __shfl_down_sync(FULLM, v, off);
        if (lane == 0) invn[r] = 1.0f / fmaxf(sqrtf(v), 1e-12f);
    }
    __syncthreads();
    for (int i = tid; i < 6144; i += 256) xn[i] *= invn[i >> 7];
    __syncthreads();

    int e = tid & 63, rg = tid >> 6;
    float acc0 = 0.f, acc1 = 0.f, acc2 = 0.f, acc3 = 0.f;
    const float* xr = xn + rg * 4 * 384;
    for (int q = 0; q < 384; q++) {
        float wv = g_convW[q * 64 + e];
        acc0 += xr[q] * wv;
        acc1 += xr[q + 384] * wv;
        acc2 += xr[q + 768] * wv;
        acc3 += xr[q + 1152] * wv;
    }
    float cb = conv_b[e];
    int row0 = b * TC + seg * 16 + rg * 4;
    g_emb[(row0 + 0) * 64 + e] = acc0 + cb;
    g_emb[(row0 + 1) * 64 + e] = acc1 + cb;
    g_emb[(row0 + 2) * 64 + e] = acc2 + cb;
    g_emb[(row0 + 3) * 64 + e] = acc3 + cb;
}

// ---------------- K2a/K2b ----------------
__global__ __launch_bounds__(256) void k2a_stats() {
    __shared__ float ps[256], pss[256];
    int tid = threadIdx.x;
    int r0 = blockIdx.x * 64;
    int e = tid & 63, qr = tid >> 6;
    float s = 0.f, ss = 0.f;
    for (int u = 0; u < 16; u++) {
        float v = g_emb[(r0 + qr * 16 + u) * 64 + e];
        s += v; ss += v * v;
    }
    ps[tid] = s; pss[tid] = ss;
    __syncthreads();
    if (tid < 64) {
        s  = ps[tid]  + ps[tid + 64]  + ps[tid + 128]  + ps[tid + 192];
        ss = pss[tid] + pss[tid + 64] + pss[tid + 128] + pss[tid + 192];
        g_part_s[blockIdx.x * 64 + tid] = s;
        g_part_ss[blockIdx.x * 64 + tid] = ss;
    }
}

__global__ __launch_bounds__(64) void k2b_finalize(
    const float* __restrict__ gamma, const float* __restrict__ beta) {
    int e = threadIdx.x;
    float s = 0.f, ss = 0.f;
    for (int blk = 0; blk < 256; blk++) {
        s  += g_part_s[blk * 64 + e];
        ss += g_part_ss[blk * 64 + e];
    }
    const float inv_n = 1.0f / 16384.0f;
    float mean = s * inv_n;
    float var = ss * inv_n - mean * mean;
    float sc = gamma[e] * rsqrtf(var + 1e-5f);
    g_scale[e] = sc;
    g_shift[e] = beta[e] - mean * sc;
}

// ---------------- K3: zx with permuted columns ----------------
__global__ __launch_bounds__(256) void k3_zx() {
    __shared__ float act[512];
    int tid = threadIdx.x;
    int r0 = blockIdx.x * 8;
    for (int i = tid; i < 512; i += 256) {
        int rr = i >> 6, e = i & 63;
        float a = g_emb[(r0 + rr) * 64 + e];
        act[i] = fmaxf(a * g_scale[e] + g_shift[e], 0.f);
    }
    __syncthreads();
    int j0 = tid, j1 = tid + 256;
    // permuted destinations: j' = (j&127)*4 + (j>>7)
    int jp0 = ((j0 & 127) << 2) | (j0 >> 7);
    int jp1 = ((j1 & 127) << 2) | (j1 >> 7);
    float acc0[8], acc1[8];
    float b0 = g_bias[jp0], b1 = g_bias[jp1];
    #pragma unroll
    for (int u = 0; u < 8; u++) { acc0[u] = b0; acc1[u] = b1; }
    for (int e = 0; e < 64; e++) {
        float w0 = g_wihT[e * 512 + j0];
        float w1 = g_wihT[e * 512 + j1];
        #pragma unroll
        for (int u = 0; u < 8; u++) {
            float a = act[u * 64 + e];
            acc0[u] += a * w0;
            acc1[u] += a * w1;
        }
    }
    #pragma unroll
    for (int u = 0; u < 8; u++) {
        float* zr = g_zx + ((size_t)(r0 + u)) * 512;
        zr[jp0] = acc0[u];
        zr[jp1] = acc1[u];
    }
}

// ---------------- K4: recurrent scan (512 threads) ----------------
#define GS_STRIDE 68
#define MS_STRIDE 65
// smem float offsets
#define OF_GS   0
#define OF_MS   8704
#define OF_LN   12864
#define OF_OS   17024
#define OF_SS   17152
#define OF_AI   17280
#define OF_AF   17408
#define OF_AG   17536
#define OF_H    17664
#define OF_C    17792
#define OF_WV   17920
#define OF_DINV 17984
#define OF_DVAL 18048
#define OF_WHH  18112
#define SMEM_FLOATS (18112 + 32768)   // 50880 floats = 203520 B

__global__ __launch_bounds__(512) void k4_scan(
    const float* __restrict__ lin_w, const float* __restrict__ lin_b,
    const float* __restrict__ wih, float* __restrict__ out) {
    extern __shared__ float sm[];
    float* Gs   = sm + OF_GS;
    float* Ms   = sm + OF_MS;
    float* Ln   = sm + OF_LN;
    float* o_s  = sm + OF_OS;
    float* s_s  = sm + OF_SS;
    float* ai   = sm + OF_AI;
    float* af   = sm + OF_AF;
    float* ag   = sm + OF_AG;
    float* h_sm = sm + OF_H;
    float* c_sm = sm + OF_C;
    float* wv   = sm + OF_WV;
    float* dinv = sm + OF_DINV;
    float* dval = sm + OF_DVAL;
    float* whh_sm = sm + OF_WHH;      // rows h=0..63 of g_whhT

    int tid = threadIdx.x;
    int b = blockIdx.x;
    int warp = tid >> 5, lane = tid & 31;

    // triangular 2x4 tile map: 32 p-tiles (2 rows) x 16 q-tiles (4 cols),
    // keep tiles intersecting the upper triangle: 4*tq+3 >= 2*tp
    int tp_s = 0, tq_s = 0; bool has_tile = false;
    {
        int idx = tid;
        #pragma unroll 1
        for (int p = 0; p < 32; p++) {
            int qmin = (2 * p - 3 + 3) >> 2;       // ceil((2p-3)/4)
            if (qmin < 0) qmin = 0;
            int wdt = 16 - qmin;
            if (idx < wdt) { tp_s = p; tq_s = qmin + idx; has_tile = true; break; }
            idx -= wdt;
        }
    }

    // preload whhT rows 0..63 into smem (coalesced float4)
    {
        const float4* srcw = (const float4*)g_whhT;
        float4* dstw = (float4*)whh_sm;
        for (int i = tid; i < 8192; i += 512) dstw[i] = srcw[i];
    }
    if (tid < 128) { h_sm[tid] = 0.f; c_sm[tid] = 0.f; }
    __syncthreads();

    for (int t = 0; t < TC; t++) {
        // ---- phase 1: z = zx + h @ whhT (j-quad x h-quarter); fused gates/coefs ----
        {
            int jq = tid & 127, quarter = tid >> 7;
            float4 zz4 = make_float4(0.f, 0.f, 0.f, 0.f);
            if (quarter == 0)
                zz4 = ((const float4*)(g_zx + ((size_t)(b * TC + t)) * 512))[jq];
            float4 acc = make_float4(0.f, 0.f, 0.f, 0.f);
            int h0 = quarter * 32;
            const float4* w4 = (quarter < 2)
                ? ((const float4*)whh_sm + jq)
                : ((const float4*)g_whhT + jq);
            #pragma unroll 8
            for (int hh = 0; hh < 32; hh++) {
                float hv = h_sm[h0 + hh];
                float4 w = w4[(h0 + hh) * 128];
                acc.x += hv * w.x; acc.y += hv * w.y;
                acc.z += hv * w.z; acc.w += hv * w.w;
            }
            float4* buf = (float4*)Ms;  // Ms/Ln dead here
            if (quarter > 0) buf[(quarter - 1) * 128 + jq] = acc;
            __syncthreads();
            if (quarter == 0) {
                float4 p0 = buf[jq], p1 = buf[128 + jq], p2 = buf[256 + jq];
                acc.x += zz4.x + p0.x + p1.x + p2.x;
                acc.y += zz4.y + p0.y + p1.y + p2.y;
                acc.z += zz4.z + p0.z + p1.z + p2.z;
                acc.w += zz4.w + p0.w + p1.w + p2.w;
                int h = jq;
                float iv = sigf(acc.x);
                float fv = sigf(acc.y);
                float gv = tanhf(acc.z);
                float ov = sigf(acc.w);
                float cv = c_sm[h];
                s_s[h] = fv * cv + iv * gv;
                ai[h] = iv * (1.f - iv) * gv;
                af[h] = fv * (1.f - fv) * cv;
                ag[h] = iv * (1.f - gv * gv);
                o_s[h] = ov;
            }
        }
        __syncthreads();

        // ---- phase 3: G build, float4, all 512 threads ----
        {
            #pragma unroll
            for (int rep = 0; rep < 4; rep++) {
                int q = tid + rep * 512;
                int h = q >> 4, e4 = (q & 15) * 4;
                float a1 = ai[h], a2 = af[h], a3 = ag[h];
                float4 wi = *(const float4*)(wih + h * 64 + e4);
                float4 wf = *(const float4*)(wih + (128 + h) * 64 + e4);
                float4 wg = *(const float4*)(wih + (256 + h) * 64 + e4);
                float4 g;
                g.x = a1 * wi.x + a2 * wf.x + a3 * wg.x;
                g.y = a1 * wi.y + a2 * wf.y + a3 * wg.y;
                g.z = a1 * wi.z + a2 * wf.z + a3 * wg.z;
                g.w = a1 * wi.w + a2 * wf.w + a3 * wg.w;
                *(float4*)(Gs + h * GS_STRIDE + e4) = g;
            }
        }
        __syncthreads();

        // ---- phase 4: M = I + eps*G^T G (tri 2x4 tiles, f32x2) ; w = G^T s on spare ----
        if (has_tile) {
            int pm = tp_s * 2, qm = tq_s * 4;
            unsigned long long a0q01 = 0ULL, a0q23 = 0ULL, a1q01 = 0ULL, a1q23 = 0ULL;
            for (int h = 0; h < 128; h++) {
                float2 gp = *(const float2*)(Gs + h * GS_STRIDE + pm);
                float4 gq = *(const float4*)(Gs + h * GS_STRIDE + qm);
                unsigned long long q01 = pk2(gq.x, gq.y);
                unsigned long long q23 = pk2(gq.z, gq.w);
                unsigned long long p0 = pk2(gp.x, gp.x);
                unsigned long long p1 = pk2(gp.y, gp.y);
                a0q01 = fma2(p0, q01, a0q01);
                a0q23 = fma2(p0, q23, a0q23);
                a1q01 = fma2(p1, q01, a1q01);
                a1q23 = fma2(p1, q23, a1q23);
            }
            float m[2][4];
            upk2(a0q01, m[0][0], m[0][1]); upk2(a0q23, m[0][2], m[0][3]);
            upk2(a1q01, m[1][0], m[1][1]); upk2(a1q23, m[1][2], m[1][3]);
            #pragma unroll
            for (int a = 0; a < 2; a++)
                #pragma unroll
                for (int c = 0; c < 4; c++) {
                    int ri = pm + a, ci = qm + c;
                    float v = EPSP * m[a][c] + (ri == ci ? 1.f : 0.f);
                    Ms[ri * MS_STRIDE + ci] = v;
                    Ms[ci * MS_STRIDE + ri] = v;
                }
        } else if (tid >= 272 && tid < 336) {
            int e = tid - 272;
            float acc = 0.f;
            for (int h = 0; h < 128; h++) acc += Gs[h * GS_STRIDE + e] * s_s[h];
            wv[e] = acc;
        }
        __syncthreads();

        // ---- panel LDL^T: phase A register-resident on warp 0 ----
        #pragma unroll 1
        for (int pp = 0; pp < 8; pp++) {
            int p0 = pp * 8;
            if (warp == 0) {
                int row0 = p0 + lane;
                int row1 = p0 + 32 + lane;
                bool act0 = row0 < 64;
                bool act1 = row1 < 64;
                float r0c[8], r1c[8], v0 = 0.f, v1 = 0.f;
                if (act0) {
                    #pragma unroll
                    for (int c = 0; c < 8; c++) r0c[c] = Ms[row0 * MS_STRIDE + p0 + c];
                    v0 = wv[row0];
                }
                if (act1) {
                    #pragma unroll
                    for (int c = 0; c < 8; c++) r1c[c] = Ms[row1 * MS_STRIDE + p0 + c];
                    v1 = wv[row1];
                }
                #pragma unroll
                for (int kl = 0; kl < 8; kl++) {
                    int k = p0 + kl;
                    float dk = __shfl_sync(FULLM, r0c[kl], kl);
                    float vk = __shfl_sync(FULLM, v0, kl);
                    float piv[8];
                    #pragma unroll
                    for (int c = 0; c < 8; c++) piv[c] = __shfl_sync(FULLM, r0c[c], kl);
                    float invd = __fdividef(1.0f, dk);
                    if (lane == kl) { dinv[k] = invd; dval[k] = dk; }
                    if (act0 && row0 > k) {
                        float lv = r0c[kl] * invd;
                        Ln[row0 * MS_STRIDE + k] = lv;
                        v0 -= lv * vk;
                        #pragma unroll
                        for (int c = 0; c < 8; c++) if (c > kl) r0c[c] -= lv * piv[c];
                    }
                    if (act1) {
                        float lv = r1c[kl] * invd;
                        Ln[row1 * MS_STRIDE + k] = lv;
                        v1 -= lv * vk;
                        #pragma unroll
                        for (int c = 0; c < 8; c++) if (c > kl) r1c[c] -= lv * piv[c];
                    }
                }
                if (act0) wv[row0] = v0;
                if (act1) wv[row1] = v1;
            }
            __syncthreads();

            // phase B: rank-8 trailing update (16 warps)
            int r0 = p0 + 8;
            if (r0 < 64) {
                for (int jq = warp; jq * 4 < 64 - r0; jq += 16) {
                    int jb = r0 + jq * 4;
                    float lrd[4][8];
                    #pragma unroll
                    for (int u = 0; u < 4; u++)
                        #pragma unroll
                        for (int c = 0; c < 8; c++)
                            lrd[u][c] = Ln[(jb + u) * MS_STRIDE + p0 + c] * dval[p0 + c];
                    for (int i = r0 + lane; i < 64; i += 32) {
                        float a[8];
                        #pragma unroll
                        for (int c = 0; c < 8; c++) a[c] = Ln[i * MS_STRIDE + p0 + c];
                        #pragma unroll
                        for (int u = 0; u < 4; u++) {
                            int j = jb + u;
                            float acc = Ms[j * MS_STRIDE + i];
                            #pragma unroll
                            for (int c = 0; c < 8; c++) acc -= lrd[u][c] * a[c];
                            Ms[j * MS_STRIDE + i] = acc;
                        }
                    }
                }
                __syncthreads();
            }
        }

        // ---- back solve (warp 0, register-resident) ----
        if (warp == 0) {
            float x0 = wv[lane] * dinv[lane];
            float x1 = wv[lane + 32] * dinv[lane + 32];
            #pragma unroll 1
            for (int k = 63; k >= 32; k--) {
                float xk = __shfl_sync(FULLM, x1, k - 32);
                if (lane + 32 < k) x1 -= Ln[k * MS_STRIDE + lane + 32] * xk;
                x0 -= Ln[k * MS_STRIDE + lane] * xk;
            }
            #pragma unroll 1
            for (int k = 31; k >= 1; k--) {
                float xk = __shfl_sync(FULLM, x0, k);
                if (lane < k) x0 -= Ln[k * MS_STRIDE + lane] * xk;
            }
            wv[lane] = x0;
            wv[lane + 32] = x1;
        }
        __syncthreads();

        // ---- epilogue: c = s - eps*G*x ; h = o*tanh(c) ----
        if (tid < 128) {
            const float4* gr = (const float4*)(Gs + tid * GS_STRIDE);
            const float4* wr = (const float4*)wv;
            float acc = 0.f;
            #pragma unroll
            for (int q = 0; q < 16; q++) {
                float4 g4 = gr[q];
                float4 w4 = wr[q];
                acc += g4.x * w4.x + g4.y * w4.y + g4.z * w4.z + g4.w * w4.w;
            }
            float cn = s_s[tid] - EPSP * acc;
            c_sm[tid] = cn;
            h_sm[tid] = o_s[tid] * tanhf(cn);
        }
        __syncthreads();
    }

    if (tid < ODIM) {
        float acc = lin_b[tid];
        for (int k = 0; k < 128; k++) acc += h_sm[k] * lin_w[tid * 128 + k];
        out[b * ODIM + tid] = acc;
    }
}

extern "C" void kernel_launch(void* const* d_in, const int* in_sizes, int n_in,
                              void* d_out, int out_size) {
    const float* inputs  = (const float*)d_in[0];
    const float* conv_w  = (const float*)d_in[2];
    const float* conv_b  = (const float*)d_in[3];
    const float* bn_g    = (const float*)d_in[4];
    const float* bn_b    = (const float*)d_in[5];
    const float* w_ih    = (const float*)d_in[6];
    const float* w_hh    = (const float*)d_in[7];
    const float* b_ih    = (const float*)d_in[8];
    const float* b_hh    = (const float*)d_in[9];
    const float* lin_w   = (const float*)d_in[10];
    const float* lin_b   = (const float*)d_in[11];
    float* out = (float*)d_out;

    cudaFuncSetAttribute(k4_scan, cudaFuncAttributeMaxDynamicSharedMemorySize,
                         SMEM_FLOATS * 4);

    k0_prep<<<483, 256>>>(w_ih, w_hh, b_ih, b_hh, conv_w);
    k1_conv<<<1024, 256>>>(inputs, conv_b);
    k2a_stats<<<256, 256>>>();
    k2b_finalize<<<1, 64>>>(bn_g, bn_b);
    k3_zx<<<2048, 256>>>();
    k4_scan<<<64, 512, SMEM_FLOATS * 4>>>(lin_w, lin_b, w_ih, out);
}

// round 16
// speedup vs baseline: 1.0825x; 1.0825x over previous
#include <cuda_runtime.h>
#include <cuda_bf16.h>
#include <cstdint>
#include <math.h>

#define BDIM 64
#define TDIM 768
#define DDIM 128
#define EDIM 64
#define HDIM 128
#define ODIM 10
#define TC   256
#define G4   512
#define EPSP 5.0f
#define FULLM 0xffffffffu

__device__ __align__(16) float g_emb[BDIM * TC * EDIM];
__device__ __align__(16) float g_zx[(size_t)BDIM * TC * G4];   // permuted cols j' = 4h+g
__device__ __align__(16) float g_whhT[HDIM * G4];              // [hsum][j'=4h+g]
__device__ __align__(16) float g_wihT[EDIM * G4];              // [e][j] orig order (k3 only)
__device__ __align__(16) float g_convW[384 * EDIM];
__device__ __align__(16) float g_bias[G4];                     // permuted [j'=4h+g]
__device__ float g_part_s[256 * EDIM];
__device__ float g_part_ss[256 * EDIM];
__device__ float g_scale[EDIM];
__device__ float g_shift[EDIM];

__device__ __forceinline__ float sigf(float x) { return 1.0f / (1.0f + expf(-x)); }

__device__ __forceinline__ unsigned long long pk2(float lo, float hi) {
    unsigned long long d; asm("mov.b64 %0, {%1,%2};" : "=l"(d) : "f"(lo), "f"(hi)); return d;
}
__device__ __forceinline__ void upk2(unsigned long long v, float& lo, float& hi) {
    asm("mov.b64 {%0,%1}, %2;" : "=f"(lo), "=f"(hi) : "l"(v));
}
__device__ __forceinline__ unsigned long long fma2(unsigned long long a, unsigned long long b, unsigned long long c) {
    unsigned long long d; asm("fma.rn.f32x2 %0, %1, %2, %3;" : "=l"(d) : "l"(a), "l"(b), "l"(c)); return d;
}

// ---------------- K0 ----------------
__global__ __launch_bounds__(256) void k0_prep(
    const float* __restrict__ wih, const float* __restrict__ whh,
    const float* __restrict__ bih, const float* __restrict__ bhh,
    const float* __restrict__ conv_w) {
    int i = blockIdx.x * 256 + threadIdx.x;
    if (i < 65536) {                       // whhT[hsum][4h+g] = whh[g*128+h][hsum]
        int hsum = i >> 9, jp = i & 511;
        int h = jp >> 2, g = jp & 3;
        g_whhT[i] = whh[((g << 7) + h) * HDIM + hsum];
    } else if (i < 65536 + 32768) {        // wihT[e][j] orig order
        int m = i - 65536;
        int e = m >> 9, j = m & 511;
        g_wihT[m] = wih[j * EDIM + e];
    } else if (i < 65536 + 32768 + 24576) {
        int m = i - 65536 - 32768;
        int q = m >> 6, e = m & 63;
        int k = q >> 7, d = q & 127;
        g_convW[m] = conv_w[e * 384 + d * 3 + k];
    } else if (i < 65536 + 32768 + 24576 + 512) {
        int jp = i - 65536 - 32768 - 24576;
        int h = jp >> 2, g = jp & 3;
        int r = (g << 7) + h;
        g_bias[jp] = bih[r] + bhh[r];
    }
}

// ---------------- K1 ----------------
__global__ __launch_bounds__(256) void k1_conv(
    const float* __restrict__ in, const float* __restrict__ conv_b) {
    __shared__ float xn[48 * 128];
    __shared__ float invn[48];
    int tid = threadIdx.x;
    int b = blockIdx.x >> 4, seg = blockIdx.x & 15;

    const float4* src = (const float4*)(in + ((size_t)b * TDIM + seg * 48) * DDIM);
    float4* d4 = (float4*)xn;
    for (int i = tid; i < 1536; i += 256) d4[i] = src[i];
    __syncthreads();

    int warp = tid >> 5, lane = tid & 31;
    for (int r = warp; r < 48; r += 8) {
        float v = 0.f;
        #pragma unroll
        for (int q = 0; q < 4; q++) { float x = xn[r * 128 + lane + q * 32]; v += x * x; }
        #pragma unroll
        for (int off = 16; off; off >>= 1) v += __shfl_down_sync(FULLM, v, off);
        if (lane == 0) invn[r] = 1.0f / fmaxf(sqrtf(v), 1e-12f);
    }
    __syncthreads();
    for (int i = tid; i < 6144; i += 256) xn[i] *= invn[i >> 7];
    __syncthreads();

    int e = tid & 63, rg = tid >> 6;
    float acc0 = 0.f, acc1 = 0.f, acc2 = 0.f, acc3 = 0.f;
    const float* xr = xn + rg * 4 * 384;
    for (int q = 0; q < 384; q++) {
        float wv = g_convW[q * 64 + e];
        acc0 += xr[q] * wv;
        acc1 += xr[q + 384] * wv;
        acc2 += xr[q + 768] * wv;
        acc3 += xr[q + 1152] * wv;
    }
    float cb = conv_b[e];
    int row0 = b * TC + seg * 16 + rg * 4;
    g_emb[(row0 + 0) * 64 + e] = acc0 + cb;
    g_emb[(row0 + 1) * 64 + e] = acc1 + cb;
    g_emb[(row0 + 2) * 64 + e] = acc2 + cb;
    g_emb[(row0 + 3) * 64 + e] = acc3 + cb;
}

// ---------------- K2a/K2b ----------------
__global__ __launch_bounds__(256) void k2a_stats() {
    __shared__ float ps[256], pss[256];
    int tid = threadIdx.x;
    int r0 = blockIdx.x * 64;
    int e = tid & 63, qr = tid >> 6;
    float s = 0.f, ss = 0.f;
    for (int u = 0; u < 16; u++) {
        float v = g_emb[(r0 + qr * 16 + u) * 64 + e];
        s += v; ss += v * v;
    }
    ps[tid] = s; pss[tid] = ss;
    __syncthreads();
    if (tid < 64) {
        s  = ps[tid]  + ps[tid + 64]  + ps[tid + 128]  + ps[tid + 192];
        ss = pss[tid] + pss[tid + 64] + pss[tid + 128] + pss[tid + 192];
        g_part_s[blockIdx.x * 64 + tid] = s;
        g_part_ss[blockIdx.x * 64 + tid] = ss;
    }
}

__global__ __launch_bounds__(64) void k2b_finalize(
    const float* __restrict__ gamma, const float* __restrict__ beta) {
    int e = threadIdx.x;
    float s = 0.f, ss = 0.f;
    for (int blk = 0; blk < 256; blk++) {
        s  += g_part_s[blk * 64 + e];
        ss += g_part_ss[blk * 64 + e];
    }
    const float inv_n = 1.0f / 16384.0f;
    float mean = s * inv_n;
    float var = ss * inv_n - mean * mean;
    float sc = gamma[e] * rsqrtf(var + 1e-5f);
    g_scale[e] = sc;
    g_shift[e] = beta[e] - mean * sc;
}

// ---------------- K3: zx with permuted columns ----------------
__global__ __launch_bounds__(256) void k3_zx() {
    __shared__ float act[512];
    int tid = threadIdx.x;
    int r0 = blockIdx.x * 8;
    for (int i = tid; i < 512; i += 256) {
        int rr = i >> 6, e = i & 63;
        float a = g_emb[(r0 + rr) * 64 + e];
        act[i] = fmaxf(a * g_scale[e] + g_shift[e], 0.f);
    }
    __syncthreads();
    int j0 = tid, j1 = tid + 256;
    int jp0 = ((j0 & 127) << 2) | (j0 >> 7);
    int jp1 = ((j1 & 127) << 2) | (j1 >> 7);
    float acc0[8], acc1[8];
    float b0 = g_bias[jp0], b1 = g_bias[jp1];
    #pragma unroll
    for (int u = 0; u < 8; u++) { acc0[u] = b0; acc1[u] = b1; }
    for (int e = 0; e < 64; e++) {
        float w0 = g_wihT[e * 512 + j0];
        float w1 = g_wihT[e * 512 + j1];
        #pragma unroll
        for (int u = 0; u < 8; u++) {
            float a = act[u * 64 + e];
            acc0[u] += a * w0;
            acc1[u] += a * w1;
        }
    }
    #pragma unroll
    for (int u = 0; u < 8; u++) {
        float* zr = g_zx + ((size_t)(r0 + u)) * 512;
        zr[jp0] = acc0[u];
        zr[jp1] = acc1[u];
    }
}

// ---------------- K4: recurrent scan (512 threads) ----------------
#define GS_STRIDE 68
#define MS_STRIDE 65
// smem float offsets (no whh cache — preserve L1D carveout)
#define OF_GS   0
#define OF_MS   8704
#define OF_LN   12864
#define OF_OS   17024
#define OF_SS   17152
#define OF_AI   17280
#define OF_AF   17408
#define OF_AG   17536
#define OF_H    17664
#define OF_C    17792
#define OF_WV   17920
#define OF_DINV 17984
#define OF_DVAL 18048
#define SMEM_FLOATS 18112             // 72448 B

__global__ __launch_bounds__(512) void k4_scan(
    const float* __restrict__ lin_w, const float* __restrict__ lin_b,
    const float* __restrict__ wih, float* __restrict__ out) {
    extern __shared__ float sm[];
    float* Gs   = sm + OF_GS;
    float* Ms   = sm + OF_MS;
    float* Ln   = sm + OF_LN;
    float* o_s  = sm + OF_OS;
    float* s_s  = sm + OF_SS;
    float* ai   = sm + OF_AI;
    float* af   = sm + OF_AF;
    float* ag   = sm + OF_AG;
    float* h_sm = sm + OF_H;
    float* c_sm = sm + OF_C;
    float* wv   = sm + OF_WV;
    float* dinv = sm + OF_DINV;
    float* dval = sm + OF_DVAL;

    int tid = threadIdx.x;
    int b = blockIdx.x;
    int warp = tid >> 5, lane = tid & 31;

    // triangular 4x2 tile map (R12, measured good): 16 p-tiles x 32 q-tiles, tq >= 2*tp
    int tp_s = 0, tq_s = 0; bool has_tile = false;
    {
        int idx = tid;
        #pragma unroll 1
        for (int p = 0; p < 16; p++) {
            int wdt = 32 - 2 * p;
            if (idx < wdt) { tp_s = p; tq_s = 2 * p + idx; has_tile = true; break; }
            idx -= wdt;
        }
    }

    if (tid < 128) { h_sm[tid] = 0.f; c_sm[tid] = 0.f; }
    __syncthreads();

    for (int t = 0; t < TC; t++) {
        // ---- phase 1: z = zx + h @ whhT (j-quad x h-quarter); fused gates/coefs ----
        {
            int jq = tid & 127, quarter = tid >> 7;
            float4 zz4 = make_float4(0.f, 0.f, 0.f, 0.f);
            if (quarter == 0)
                zz4 = ((const float4*)(g_zx + ((size_t)(b * TC + t)) * 512))[jq];
            float4 acc = make_float4(0.f, 0.f, 0.f, 0.f);
            const float4* w4 = (const float4*)g_whhT + jq;  // row stride 128 float4
            int h0 = quarter * 32;
            #pragma unroll 8
            for (int hh = 0; hh < 32; hh++) {
                float hv = h_sm[h0 + hh];
                float4 w = w4[(h0 + hh) * 128];
                acc.x += hv * w.x; acc.y += hv * w.y;
                acc.z += hv * w.z; acc.w += hv * w.w;
            }
            float4* buf = (float4*)Ms;  // Ms/Ln dead here
            if (quarter > 0) buf[(quarter - 1) * 128 + jq] = acc;
            __syncthreads();
            if (quarter == 0) {
                float4 p0 = buf[jq], p1 = buf[128 + jq], p2 = buf[256 + jq];
                acc.x += zz4.x + p0.x + p1.x + p2.x;
                acc.y += zz4.y + p0.y + p1.y + p2.y;
                acc.z += zz4.z + p0.z + p1.z + p2.z;
                acc.w += zz4.w + p0.w + p1.w + p2.w;
                int h = jq;
                float iv = sigf(acc.x);
                float fv = sigf(acc.y);
                float gv = tanhf(acc.z);
                float ov = sigf(acc.w);
                float cv = c_sm[h];
                s_s[h] = fv * cv + iv * gv;
                ai[h] = iv * (1.f - iv) * gv;
                af[h] = fv * (1.f - fv) * cv;
                ag[h] = iv * (1.f - gv * gv);
                o_s[h] = ov;
            }
        }
        __syncthreads();

        // ---- phase 3: G build, float4, all 512 threads ----
        {
            #pragma unroll
            for (int rep = 0; rep < 4; rep++) {
                int q = tid + rep * 512;
                int h = q >> 4, e4 = (q & 15) * 4;
                float a1 = ai[h], a2 = af[h], a3 = ag[h];
                float4 wi = *(const float4*)(wih + h * 64 + e4);
                float4 wf = *(const float4*)(wih + (128 + h) * 64 + e4);
                float4 wg = *(const float4*)(wih + (256 + h) * 64 + e4);
                float4 g;
                g.x = a1 * wi.x + a2 * wf.x + a3 * wg.x;
                g.y = a1 * wi.y + a2 * wf.y + a3 * wg.y;
                g.z = a1 * wi.z + a2 * wf.z + a3 * wg.z;
                g.w = a1 * wi.w + a2 * wf.w + a3 * wg.w;
                *(float4*)(Gs + h * GS_STRIDE + e4) = g;
            }
        }
        __syncthreads();

        // ---- phase 4: M = I + eps*G^T G (tri 4x2 tiles, f32x2) ; w = G^T s on spare ----
        if (has_tile) {
            int pm = tp_s * 4, qm = tq_s * 2;
            unsigned long long acc[4] = {0ULL, 0ULL, 0ULL, 0ULL};
            for (int h = 0; h < 128; h++) {
                float4 gp = *(const float4*)(Gs + h * GS_STRIDE + pm);
                float2 gq = *(const float2*)(Gs + h * GS_STRIDE + qm);
                unsigned long long q01 = pk2(gq.x, gq.y);
                acc[0] = fma2(pk2(gp.x, gp.x), q01, acc[0]);
                acc[1] = fma2(pk2(gp.y, gp.y), q01, acc[1]);
                acc[2] = fma2(pk2(gp.z, gp.z), q01, acc[2]);
                acc[3] = fma2(pk2(gp.w, gp.w), q01, acc[3]);
            }
            #pragma unroll
            for (int a = 0; a < 4; a++) {
                float m0, m1;
                upk2(acc[a], m0, m1);
                int ri = pm + a;
                float v0 = EPSP * m0 + (ri == qm + 0 ? 1.f : 0.f);
                float v1 = EPSP * m1 + (ri == qm + 1 ? 1.f : 0.f);
                Ms[ri * MS_STRIDE + qm]       = v0;
                Ms[ri * MS_STRIDE + qm + 1]   = v1;
                Ms[qm * MS_STRIDE + ri]       = v0;
                Ms[(qm + 1) * MS_STRIDE + ri] = v1;
            }
        } else if (tid >= 272 && tid < 336) {
            int e = tid - 272;
            float acc = 0.f;
            for (int h = 0; h < 128; h++) acc += Gs[h * GS_STRIDE + e] * s_s[h];
            wv[e] = acc;
        }
        __syncthreads();

        // ---- panel LDL^T: phase A register-resident on warp 0 ----
        #pragma unroll 1
        for (int pp = 0; pp < 8; pp++) {
            int p0 = pp * 8;
            if (warp == 0) {
                int row0 = p0 + lane;
                int row1 = p0 + 32 + lane;
                bool act0 = row0 < 64;
                bool act1 = row1 < 64;
                float r0c[8], r1c[8], v0 = 0.f, v1 = 0.f;
                if (act0) {
                    #pragma unroll
                    for (int c = 0; c < 8; c++) r0c[c] = Ms[row0 * MS_STRIDE + p0 + c];
                    v0 = wv[row0];
                }
                if (act1) {
                    #pragma unroll
                    for (int c = 0; c < 8; c++) r1c[c] = Ms[row1 * MS_STRIDE + p0 + c];
                    v1 = wv[row1];
                }
                #pragma unroll
                for (int kl = 0; kl < 8; kl++) {
                    int k = p0 + kl;
                    float dk = __shfl_sync(FULLM, r0c[kl], kl);
                    float vk = __shfl_sync(FULLM, v0, kl);
                    float piv[8];
                    #pragma unroll
                    for (int c = 0; c < 8; c++) piv[c] = __shfl_sync(FULLM, r0c[c], kl);
                    float invd = __fdividef(1.0f, dk);
                    if (lane == kl) { dinv[k] = invd; dval[k] = dk; }
                    if (act0 && row0 > k) {
                        float lv = r0c[kl] * invd;
                        Ln[row0 * MS_STRIDE + k] = lv;
                        v0 -= lv * vk;
                        #pragma unroll
                        for (int c = 0; c < 8; c++) if (c > kl) r0c[c] -= lv * piv[c];
                    }
                    if (act1) {
                        float lv = r1c[kl] * invd;
                        Ln[row1 * MS_STRIDE + k] = lv;
                        v1 -= lv * vk;
                        #pragma unroll
                        for (int c = 0; c < 8; c++) if (c > kl) r1c[c] -= lv * piv[c];
                    }
                }
                if (act0) wv[row0] = v0;
                if (act1) wv[row1] = v1;
            }
            __syncthreads();

            // phase B: rank-8 trailing update (16 warps)
            int r0 = p0 + 8;
            if (r0 < 64) {
                for (int jq = warp; jq * 4 < 64 - r0; jq += 16) {
                    int jb = r0 + jq * 4;
                    float lrd[4][8];
                    #pragma unroll
                    for (int u = 0; u < 4; u++)
                        #pragma unroll
                        for (int c = 0; c < 8; c++)
                            lrd[u][c] = Ln[(jb + u) * MS_STRIDE + p0 + c] * dval[p0 + c];
                    for (int i = r0 + lane; i < 64; i += 32) {
                        float a[8];
                        #pragma unroll
                        for (int c = 0; c < 8; c++) a[c] = Ln[i * MS_STRIDE + p0 + c];
                        #pragma unroll
                        for (int u = 0; u < 4; u++) {
                            int j = jb + u;
                            float acc = Ms[j * MS_STRIDE + i];
                            #pragma unroll
                            for (int c = 0; c < 8; c++) acc -= lrd[u][c] * a[c];
                            Ms[j * MS_STRIDE + i] = acc;
                        }
                    }
                }
                __syncthreads();
            }
        }

        // ---- back solve (warp 0, register-resident) ----
        if (warp == 0) {
            float x0 = wv[lane] * dinv[lane];
            float x1 = wv[lane + 32] * dinv[lane + 32];
            #pragma unroll 1
            for (int k = 63; k >= 32; k--) {
                float xk = __shfl_sync(FULLM, x1, k - 32);
                if (lane + 32 < k) x1 -= Ln[k * MS_STRIDE + lane + 32] * xk;
                x0 -= Ln[k * MS_STRIDE + lane] * xk;
            }
            #pragma unroll 1
            for (int k = 31; k >= 1; k--) {
                float xk = __shfl_sync(FULLM, x0, k);
                if (lane < k) x0 -= Ln[k * MS_STRIDE + lane] * xk;
            }
            wv[lane] = x0;
            wv[lane + 32] = x1;
        }
        __syncthreads();

        // ---- epilogue: c = s - eps*G*x ; h = o*tanh(c) ----
        if (tid < 128) {
            const float4* gr = (const float4*)(Gs + tid * GS_STRIDE);
            const float4* wr = (const float4*)wv;
            float acc = 0.f;
            #pragma unroll
            for (int q = 0; q < 16; q++) {
                float4 g4 = gr[q];
                float4 w4 = wr[q];
                acc += g4.x * w4.x + g4.y * w4.y + g4.z * w4.z + g4.w * w4.w;
            }
            float cn = s_s[tid] - EPSP * acc;
            c_sm[tid] = cn;
            h_sm[tid] = o_s[tid] * tanhf(cn);
        }
        __syncthreads();
    }

    if (tid < ODIM) {
        float acc = lin_b[tid];
        for (int k = 0; k < 128; k++) acc += h_sm[k] * lin_w[tid * 128 + k];
        out[b * ODIM + tid] = acc;
    }
}

extern "C" void kernel_launch(void* const* d_in, const int* in_sizes, int n_in,
                              void* d_out, int out_size) {
    const float* inputs  = (const float*)d_in[0];
    const float* conv_w  = (const float*)d_in[2];
    const float* conv_b  = (const float*)d_in[3];
    const float* bn_g    = (const float*)d_in[4];
    const float* bn_b    = (const float*)d_in[5];
    const float* w_ih    = (const float*)d_in[6];
    const float* w_hh    = (const float*)d_in[7];
    const float* b_ih    = (const float*)d_in[8];
    const float* b_hh    = (const float*)d_in[9];
    const float* lin_w   = (const float*)d_in[10];
    const float* lin_b   = (const float*)d_in[11];
    float* out = (float*)d_out;

    cudaFuncSetAttribute(k4_scan, cudaFuncAttributeMaxDynamicSharedMemorySize,
                         SMEM_FLOATS * 4);

    k0_prep<<<483, 256>>>(w_ih, w_hh, b_ih, b_hh, conv_w);
    k1_conv<<<1024, 256>>>(inputs, conv_b);
    k2a_stats<<<256, 256>>>();
    k2b_finalize<<<1, 64>>>(bn_g, bn_b);
    k3_zx<<<2048, 256>>>();
    k4_scan<<<64, 512, SMEM_FLOATS * 4>>>(lin_w, lin_b, w_ih, out);
}